// round 14
// baseline (speedup 1.0000x reference)
#include <cuda_runtime.h>
#include <cuda_fp16.h>
#include <cstdint>

#define DEV_INLINE __device__ __forceinline__

constexpr int NN = 8192;   // nodes
constexpr int DF = 256;    // feature dim
constexpr float YSCALE = 4096.f;   // exact pow2: keeps Y out of fp16 subnormals

// ---------------- intermediates (static device globals; no runtime alloc) ----
__device__ float  g_inv_deg[NN];
__device__ __half g_ysTh[(size_t)DF * NN];   // [d][j] = fp16( YSCALE*inv_j*(xW)[j][d] )

// ============================================================================
// helpers (baseline sm_103 ISA only: cp.async, ldmatrix, mma.sync)
// ============================================================================
DEV_INLINE uint32_t smem_u32(const void* p) {
    uint32_t a;
    asm("{ .reg .u64 t; cvta.to.shared.u64 t, %1; cvt.u32.u64 %0, t; }" : "=r"(a) : "l"(p));
    return a;
}
DEV_INLINE void cp16(uint32_t saddr, const void* g) {
    asm volatile("cp.async.cg.shared.global [%0], [%1], 16;" :: "r"(saddr), "l"(g));
}
DEV_INLINE void cp_commit() { asm volatile("cp.async.commit_group;"); }
template <int N> DEV_INLINE void cp_wait() { asm volatile("cp.async.wait_group %0;" :: "n"(N)); }

DEV_INLINE void ldsm4(uint32_t* d, uint32_t addr) {
    asm volatile("ldmatrix.sync.aligned.m8n8.x4.shared.b16 {%0,%1,%2,%3}, [%4];"
                 : "=r"(d[0]), "=r"(d[1]), "=r"(d[2]), "=r"(d[3]) : "r"(addr));
}
DEV_INLINE void ldsm4t(uint32_t* d, uint32_t addr) {
    asm volatile("ldmatrix.sync.aligned.m8n8.x4.trans.shared.b16 {%0,%1,%2,%3}, [%4];"
                 : "=r"(d[0]), "=r"(d[1]), "=r"(d[2]), "=r"(d[3]) : "r"(addr));
}
DEV_INLINE void mma_f16(float* c, const uint32_t* a, const uint32_t* b) {
    asm volatile(
        "mma.sync.aligned.m16n8k16.row.col.f32.f16.f16.f32 "
        "{%0,%1,%2,%3}, {%4,%5,%6,%7}, {%8,%9}, {%0,%1,%2,%3};"
        : "+f"(c[0]), "+f"(c[1]), "+f"(c[2]), "+f"(c[3])
        : "r"(a[0]), "r"(a[1]), "r"(a[2]), "r"(a[3]), "r"(b[0]), "r"(b[1]));
}

// ============================================================================
// Kernel 1: inv_deg[i] = 1/rowsum(A[i,:])   — pure read, 268 MB (~41.5 us)
// ============================================================================
__global__ void __launch_bounds__(256) rowsum_kernel(const float* __restrict__ A) {
    int row = blockIdx.x;
    const float4* r4 = reinterpret_cast<const float4*>(A + (size_t)row * NN);
    float s = 0.f;
#pragma unroll
    for (int it = 0; it < (NN / 4) / 256; it++) {
        float4 v = r4[it * 256 + threadIdx.x];
        s += (v.x + v.y) + (v.z + v.w);
    }
    __shared__ float red[256];
    red[threadIdx.x] = s;
    __syncthreads();
#pragma unroll
    for (int o = 128; o > 0; o >>= 1) {
        if (threadIdx.x < o) red[threadIdx.x] += red[threadIdx.x + o];
        __syncthreads();
    }
    if (threadIdx.x == 0) g_inv_deg[row] = 1.0f / red[0];
}

// ============================================================================
// Kernel 2 (tensor-core): ysTh[d][j] = fp16( YSCALE*inv_j * sum_k W[k][d] x[j][k] )
// [R11, unchanged — measured ~7us]
// ============================================================================
constexpr int XROWW = (128 + 8) * 2;
constexpr int XROWX = (64 + 8) * 2;
constexpr int XW_TILE_W = 64 * XROWW;
constexpr int XW_TILE_X = 128 * XROWX;
constexpr int SMEM_XW = XW_TILE_W + XW_TILE_X + 128 * 4 + 256;

__global__ void __launch_bounds__(512, 1) xw_tensor_kernel(const float* __restrict__ x,
                                                           const float* __restrict__ W) {
    extern __shared__ char smem[];
    const uint32_t sW = smem_u32(smem);
    const uint32_t sX = sW + XW_TILE_W;
    float* ivd = reinterpret_cast<float*>(smem + XW_TILE_W + XW_TILE_X);

    const int tid  = threadIdx.x;
    const int wid  = tid >> 5;
    const int lane = tid & 31;
    const int wm   = wid >> 2;
    const int wn   = wid & 3;
    const int jbase = blockIdx.x * 128;
    const int dbase = blockIdx.y * 128;

    if (tid < 128) ivd[tid] = g_inv_deg[jbase + tid] * YSCALE;

    const int g2 = lane >> 2, t2 = lane & 3;
    const int q = lane >> 3, r = lane & 7;
    const uint32_t boff = (uint32_t)((wn * 32 + (q >> 1) * 8 + r) * XROWX + (q & 1) * 16);

    float4 regW[4], regX[4];
    auto ldgW = [&](int kt) {
        const int k0 = kt * 64;
#pragma unroll
        for (int i = 0; i < 4; i++) {
            int c = i * 512 + tid;
            regW[i] = *reinterpret_cast<const float4*>(
                W + (size_t)(k0 + (c >> 5)) * DF + dbase + (c & 31) * 4);
        }
    };
    auto ldgX = [&](int kt) {
        const int k0 = kt * 64;
#pragma unroll
        for (int i = 0; i < 4; i++) {
            int c = i * 512 + tid;
            regX[i] = *reinterpret_cast<const float4*>(
                x + (size_t)(jbase + (c >> 4)) * DF + k0 + (c & 15) * 4);
        }
    };
    auto stsAll = [&]() {
#pragma unroll
        for (int i = 0; i < 4; i++) {
            int c = i * 512 + tid;
            union { __half2 h[2]; uint2 u; } p;
            p.h[0] = __floats2half2_rn(regW[i].x, regW[i].y);
            p.h[1] = __floats2half2_rn(regW[i].z, regW[i].w);
            asm volatile("st.shared.v2.u32 [%0], {%1,%2};"
                         :: "r"(sW + (c >> 5) * XROWW + (c & 31) * 8),
                            "r"(p.u.x), "r"(p.u.y) : "memory");
            union { __half2 h[2]; uint2 u; } px;
            px.h[0] = __floats2half2_rn(regX[i].x, regX[i].y);
            px.h[1] = __floats2half2_rn(regX[i].z, regX[i].w);
            asm volatile("st.shared.v2.u32 [%0], {%1,%2};"
                         :: "r"(sX + (c >> 4) * XROWX + (c & 15) * 8),
                            "r"(px.u.x), "r"(px.u.y) : "memory");
        }
    };

    float acc[2][4][4];
#pragma unroll
    for (int mt = 0; mt < 2; mt++)
#pragma unroll
        for (int nt = 0; nt < 4; nt++)
#pragma unroll
            for (int i = 0; i < 4; i++) acc[mt][nt][i] = 0.f;

    ldgW(0); ldgX(0);
    for (int kt = 0; kt < 4; kt++) {
        __syncthreads();
        stsAll();
        if (kt + 1 < 4) { ldgW(kt + 1); ldgX(kt + 1); }
        __syncthreads();
#pragma unroll
        for (int ks = 0; ks < 4; ks++) {
            uint32_t afr[2][4];
#pragma unroll
            for (int mt = 0; mt < 2; mt++) {
                uint32_t ap = sW + (uint32_t)((ks * 16 + (q >> 1) * 8 + r) * XROWW
                              + (wm * 32 + mt * 16 + (q & 1) * 8) * 2);
                ldsm4t(afr[mt], ap);
            }
            uint32_t bfr[2][4];
#pragma unroll
            for (int np = 0; np < 2; np++)
                ldsm4(bfr[np], sX + boff + np * (16 * XROWX) + ks * 32);
#pragma unroll
            for (int mt = 0; mt < 2; mt++)
#pragma unroll
                for (int nt = 0; nt < 4; nt++)
                    mma_f16(acc[mt][nt], afr[mt], &bfr[nt >> 1][(nt & 1) * 2]);
        }
    }

#pragma unroll
    for (int mt = 0; mt < 2; mt++) {
        const int d0 = dbase + wm * 32 + mt * 16 + g2;
#pragma unroll
        for (int nt = 0; nt < 4; nt++) {
            const int cl = wn * 32 + nt * 8 + t2 * 2;
            const float v0 = ivd[cl], v1 = ivd[cl + 1];
            union { __half2 h; uint32_t u; } p0, p1;
            p0.h = __floats2half2_rn(acc[mt][nt][0] * v0, acc[mt][nt][1] * v1);
            p1.h = __floats2half2_rn(acc[mt][nt][2] * v0, acc[mt][nt][3] * v1);
            *reinterpret_cast<uint32_t*>(&g_ysTh[(size_t)d0 * NN + jbase + cl]) = p0.u;
            *reinterpret_cast<uint32_t*>(&g_ysTh[(size_t)(d0 + 8) * NN + jbase + cl]) = p1.u;
        }
    }
}

// ============================================================================
// Kernel 3: out = relu( (inv_deg_i/YSCALE) * (A @ Yh) + bias )
// Monolithic fp16 mma.sync GEMM, A consumed as fp32 via cp.async + a block-
// wide smem convert pass into a single fp16 staging buffer (ldmatrix layout).
// BM=128, BN=128, BK=64, 3-stage, 512 threads, grid 64x2 (single wave).
// ============================================================================
constexpr int BM = 128, BN = 128, BK = 64;
constexpr int STAGES = 3;
constexpr int NK = NN / BK;                   // 128
constexpr int ROWA32 = (BK + 8) * 4;          // fp32 A row: 288 B
constexpr int ROWH   = (BK + 8) * 2;          // fp16 row: 144 B
constexpr int A32_TILE = BM * ROWA32;         // 36864
constexpr int B_TILE   = BN * ROWH;           // 18432
constexpr int STAGE_B  = A32_TILE + B_TILE;   // 55296
constexpr int AH_OFF   = STAGES * STAGE_B;    // fp16 A staging buffer
constexpr int AH_TILE  = BM * ROWH;           // 18432
constexpr int SMEM_GEMM = AH_OFF + AH_TILE + 2 * BM * 4;   // 185344

__global__ void __launch_bounds__(512, 1) gcn_gemm_kernel(const float* __restrict__ A,
                                                          const float* __restrict__ bias,
                                                          float* __restrict__ out) {
    extern __shared__ char smem[];
    const uint32_t sbase = smem_u32(smem);
    const uint32_t sAH   = sbase + AH_OFF;
    float* invd_s = reinterpret_cast<float*>(smem + AH_OFF + AH_TILE);
    float* bias_s = invd_s + BM;

    const int tid  = threadIdx.x;
    const int wid  = tid >> 5;
    const int lane = tid & 31;
    const int wm   = wid >> 2;
    const int wn   = wid & 3;
    const int mbase = blockIdx.x * BM;
    const int nbase = blockIdx.y * BN;

    if (tid < BM) {
        invd_s[tid] = g_inv_deg[mbase + tid] * (1.0f / YSCALE);
        bias_s[tid] = bias[nbase + tid];
    }

    const int g2 = lane >> 2, t2 = lane & 3;
    const int q = lane >> 3, r = lane & 7;
    const uint32_t aoff = (uint32_t)((wm * 32 + (q & 1) * 8 + r) * ROWH + (q >> 1) * 16);
    const uint32_t boff = (uint32_t)((wn * 32 + (q >> 1) * 8 + r) * ROWH + (q & 1) * 16);

    // stage loader: A 2048 fp32 16B chunks + B 1024 fp16 16B chunks
    auto load_stage = [&](int st, int kt) {
        const uint32_t sA = sbase + st * STAGE_B;
        const uint32_t sB = sA + A32_TILE;
        const int k0 = kt * BK;
#pragma unroll
        for (int i = 0; i < 6; i++) {
            int c = i * 512 + tid;            // 0..3071
            if (c < 2048) {                   // A: 128 rows x 16 chunks fp32
                int row = c >> 4, cq = c & 15;
                cp16(sA + row * ROWA32 + cq * 16,
                     A + (size_t)(mbase + row) * NN + k0 + cq * 4);
            } else {                          // B: 128 rows x 8 chunks fp16
                int c2 = c - 2048;
                int row = c2 >> 3, cq = c2 & 7;
                cp16(sB + row * ROWH + cq * 16,
                     g_ysTh + (size_t)(nbase + row) * NN + k0 + cq * 8);
            }
        }
    };

    // convert pass: fp32 stage -> fp16 staging buffer (transient regs only)
    auto convertA = [&](int st) {
        const uint32_t sA = sbase + st * STAGE_B;
#pragma unroll
        for (int i = 0; i < 4; i++) {
            int c = i * 512 + tid;            // 0..2047
            int row = c >> 4, cq = c & 15;
            float4 v;
            asm volatile("ld.shared.v4.f32 {%0,%1,%2,%3}, [%4];"
                         : "=f"(v.x), "=f"(v.y), "=f"(v.z), "=f"(v.w)
                         : "r"(sA + row * ROWA32 + cq * 16));
            union { __half2 h[2]; uint2 u; } p;
            p.h[0] = __floats2half2_rn(v.x, v.y);
            p.h[1] = __floats2half2_rn(v.z, v.w);
            asm volatile("st.shared.v2.u32 [%0], {%1,%2};"
                         :: "r"(sAH + row * ROWH + cq * 8),
                            "r"(p.u.x), "r"(p.u.y) : "memory");
        }
    };

    float acc[2][4][4];
#pragma unroll
    for (int mt = 0; mt < 2; mt++)
#pragma unroll
        for (int nt = 0; nt < 4; nt++)
#pragma unroll
            for (int i = 0; i < 4; i++) acc[mt][nt][i] = 0.f;

    load_stage(0, 0); cp_commit();
    load_stage(1, 1); cp_commit();

    int st = 0;
    for (int kt = 0; kt < NK; kt++) {
        cp_wait<1>();
        __syncthreads();          // stage kt visible; prev-iter AH reads done

        int pst = st + 2 >= STAGES ? st + 2 - STAGES : st + 2;
        if (kt + 2 < NK) load_stage(pst, kt + 2);
        cp_commit();

        convertA(st);             // fp32 -> fp16 staging
        __syncthreads();          // AH(kt) visible to all warps

        const uint32_t sB = sbase + st * STAGE_B + A32_TILE;
#pragma unroll
        for (int ks = 0; ks < 4; ks++) {
            uint32_t afr[2][4];
#pragma unroll
            for (int mt = 0; mt < 2; mt++)
                ldsm4(afr[mt], sAH + aoff + mt * (16 * ROWH) + ks * 32);
            uint32_t bfr[2][4];
#pragma unroll
            for (int np = 0; np < 2; np++)
                ldsm4(bfr[np], sB + boff + np * (16 * ROWH) + ks * 32);
#pragma unroll
            for (int mt = 0; mt < 2; mt++)
#pragma unroll
                for (int nt = 0; nt < 4; nt++)
                    mma_f16(acc[mt][nt], afr[mt], &bfr[nt >> 1][(nt & 1) * 2]);
        }
        st = st + 1 >= STAGES ? 0 : st + 1;
    }

    // epilogue: scale by inv_deg(row)/YSCALE, add bias, relu, store float2
#pragma unroll
    for (int mt = 0; mt < 2; mt++) {
        const int rl = wm * 32 + mt * 16 + g2;
        const float s0 = invd_s[rl], s1 = invd_s[rl + 8];
        float* o0 = out + (size_t)(mbase + rl) * DF + nbase + wn * 32;
        float* o1 = o0 + (size_t)8 * DF;
#pragma unroll
        for (int nt = 0; nt < 4; nt++) {
            const int c = nt * 8 + t2 * 2;
            const float b0 = bias_s[wn * 32 + c], b1 = bias_s[wn * 32 + c + 1];
            float2 v0, v1;
            v0.x = fmaxf(fmaf(acc[mt][nt][0], s0, b0), 0.f);
            v0.y = fmaxf(fmaf(acc[mt][nt][1], s0, b1), 0.f);
            v1.x = fmaxf(fmaf(acc[mt][nt][2], s1, b0), 0.f);
            v1.y = fmaxf(fmaf(acc[mt][nt][3], s1, b1), 0.f);
            *reinterpret_cast<float2*>(o0 + c) = v0;
            *reinterpret_cast<float2*>(o1 + c) = v1;
        }
    }
}

// ============================================================================
// Launch
// ============================================================================
extern "C" void kernel_launch(void* const* d_in, const int* in_sizes, int n_in,
                              void* d_out, int out_size) {
    const float* x    = (const float*)d_in[0];   // [8192,256]
    const float* adj  = (const float*)d_in[1];   // [8192,8192]
    const float* W    = (const float*)d_in[2];   // [256,256]
    const float* bias = (const float*)d_in[3];   // [256]
    float* out = (float*)d_out;                  // [8192,256]

    cudaFuncSetAttribute(gcn_gemm_kernel, cudaFuncAttributeMaxDynamicSharedMemorySize,
                         SMEM_GEMM);
    cudaFuncSetAttribute(xw_tensor_kernel, cudaFuncAttributeMaxDynamicSharedMemorySize,
                         SMEM_XW);

    rowsum_kernel<<<NN, 256>>>(adj);
    dim3 xgrid(NN / 128, DF / 128);   // 64 x 2
    xw_tensor_kernel<<<xgrid, 512, SMEM_XW>>>(x, W);
    dim3 grid(NN / BM, DF / BN);      // 64 x 2
    gcn_gemm_kernel<<<grid, 512, SMEM_GEMM>>>(adj, bias, out);
}

// round 15
// speedup vs baseline: 1.1354x; 1.1354x over previous
#include <cuda_runtime.h>
#include <cuda_fp16.h>
#include <cstdint>

#define DEV_INLINE __device__ __forceinline__

constexpr int NN = 8192;   // nodes
constexpr int DF = 256;    // feature dim
constexpr float YSCALE = 4096.f;   // exact pow2: keeps Y out of fp16 subnormals

// ---------------- intermediates (static device globals; no runtime alloc) ----
__device__ float  g_inv_deg[NN];
__device__ __half g_Ah[(size_t)NN * NN];     // fp16 copy of adjacency (rn)
__device__ float  g_ysU[(size_t)DF * NN];    // U[d][j] = fp32( sum_k W[k][d] x[j][k] )
__device__ __half g_ysTh[(size_t)DF * NN];   // Y[d][j] = fp16( YSCALE*inv_j*U[d][j] )

// ============================================================================
// helpers (baseline sm_103 ISA only: cp.async, ldmatrix, mma.sync)
// ============================================================================
DEV_INLINE uint32_t smem_u32(const void* p) {
    uint32_t a;
    asm("{ .reg .u64 t; cvta.to.shared.u64 t, %1; cvt.u32.u64 %0, t; }" : "=r"(a) : "l"(p));
    return a;
}
DEV_INLINE void cp16(uint32_t saddr, const void* g) {
    asm volatile("cp.async.cg.shared.global [%0], [%1], 16;" :: "r"(saddr), "l"(g));
}
DEV_INLINE void cp_commit() { asm volatile("cp.async.commit_group;"); }
template <int N> DEV_INLINE void cp_wait() { asm volatile("cp.async.wait_group %0;" :: "n"(N)); }

DEV_INLINE void ldsm4(uint32_t* d, uint32_t addr) {
    asm volatile("ldmatrix.sync.aligned.m8n8.x4.shared.b16 {%0,%1,%2,%3}, [%4];"
                 : "=r"(d[0]), "=r"(d[1]), "=r"(d[2]), "=r"(d[3]) : "r"(addr));
}
DEV_INLINE void ldsm4t(uint32_t* d, uint32_t addr) {
    asm volatile("ldmatrix.sync.aligned.m8n8.x4.trans.shared.b16 {%0,%1,%2,%3}, [%4];"
                 : "=r"(d[0]), "=r"(d[1]), "=r"(d[2]), "=r"(d[3]) : "r"(addr));
}
DEV_INLINE void mma_f16(float* c, const uint32_t* a, const uint32_t* b) {
    asm volatile(
        "mma.sync.aligned.m16n8k16.row.col.f32.f16.f16.f32 "
        "{%0,%1,%2,%3}, {%4,%5,%6,%7}, {%8,%9}, {%0,%1,%2,%3};"
        : "+f"(c[0]), "+f"(c[1]), "+f"(c[2]), "+f"(c[3])
        : "r"(a[0]), "r"(a[1]), "r"(a[2]), "r"(a[3]), "r"(b[0]), "r"(b[1]));
}

// ============================================================================
// Kernel A (primary): U[d][j] = fp32( sum_k W[k][d] x[j][k] )  — no inv_deg.
// Triggers programmatic launch completion at entry so rowsum overlaps.
// ============================================================================
constexpr int XROWW = (128 + 8) * 2;
constexpr int XROWX = (64 + 8) * 2;
constexpr int XW_TILE_W = 64 * XROWW;
constexpr int XW_TILE_X = 128 * XROWX;
constexpr int SMEM_XW = XW_TILE_W + XW_TILE_X + 256;

__global__ void __launch_bounds__(512, 1) xwU_kernel(const float* __restrict__ x,
                                                     const float* __restrict__ W) {
    cudaTriggerProgrammaticLaunchCompletion();   // let rowsum start immediately

    extern __shared__ char smem[];
    const uint32_t sW = smem_u32(smem);
    const uint32_t sX = sW + XW_TILE_W;

    const int tid  = threadIdx.x;
    const int wid  = tid >> 5;
    const int lane = tid & 31;
    const int wm   = wid >> 2;
    const int wn   = wid & 3;
    const int jbase = (blockIdx.x >> 1) * 128;
    const int dbase = (blockIdx.x & 1) * 128;

    const int g2 = lane >> 2, t2 = lane & 3;
    const int q = lane >> 3, r = lane & 7;
    const uint32_t boff = (uint32_t)((wn * 32 + (q >> 1) * 8 + r) * XROWX + (q & 1) * 16);

    float4 regW[4], regX[4];
    auto ldgW = [&](int kt) {
        const int k0 = kt * 64;
#pragma unroll
        for (int i = 0; i < 4; i++) {
            int c = i * 512 + tid;
            regW[i] = *reinterpret_cast<const float4*>(
                W + (size_t)(k0 + (c >> 5)) * DF + dbase + (c & 31) * 4);
        }
    };
    auto ldgX = [&](int kt) {
        const int k0 = kt * 64;
#pragma unroll
        for (int i = 0; i < 4; i++) {
            int c = i * 512 + tid;
            regX[i] = *reinterpret_cast<const float4*>(
                x + (size_t)(jbase + (c >> 4)) * DF + k0 + (c & 15) * 4);
        }
    };
    auto stsAll = [&]() {
#pragma unroll
        for (int i = 0; i < 4; i++) {
            int c = i * 512 + tid;
            union { __half2 h[2]; uint2 u; } p;
            p.h[0] = __floats2half2_rn(regW[i].x, regW[i].y);
            p.h[1] = __floats2half2_rn(regW[i].z, regW[i].w);
            asm volatile("st.shared.v2.u32 [%0], {%1,%2};"
                         :: "r"(sW + (c >> 5) * XROWW + (c & 31) * 8),
                            "r"(p.u.x), "r"(p.u.y) : "memory");
            union { __half2 h[2]; uint2 u; } px;
            px.h[0] = __floats2half2_rn(regX[i].x, regX[i].y);
            px.h[1] = __floats2half2_rn(regX[i].z, regX[i].w);
            asm volatile("st.shared.v2.u32 [%0], {%1,%2};"
                         :: "r"(sX + (c >> 4) * XROWX + (c & 15) * 8),
                            "r"(px.u.x), "r"(px.u.y) : "memory");
        }
    };

    float acc[2][4][4];
#pragma unroll
    for (int mt = 0; mt < 2; mt++)
#pragma unroll
        for (int nt = 0; nt < 4; nt++)
#pragma unroll
            for (int i = 0; i < 4; i++) acc[mt][nt][i] = 0.f;

    ldgW(0); ldgX(0);
    for (int kt = 0; kt < 4; kt++) {
        __syncthreads();
        stsAll();
        if (kt + 1 < 4) { ldgW(kt + 1); ldgX(kt + 1); }
        __syncthreads();
#pragma unroll
        for (int ks = 0; ks < 4; ks++) {
            uint32_t afr[2][4];
#pragma unroll
            for (int mt = 0; mt < 2; mt++) {
                uint32_t ap = sW + (uint32_t)((ks * 16 + (q >> 1) * 8 + r) * XROWW
                              + (wm * 32 + mt * 16 + (q & 1) * 8) * 2);
                ldsm4t(afr[mt], ap);
            }
            uint32_t bfr[2][4];
#pragma unroll
            for (int np = 0; np < 2; np++)
                ldsm4(bfr[np], sX + boff + np * (16 * XROWX) + ks * 32);
#pragma unroll
            for (int mt = 0; mt < 2; mt++)
#pragma unroll
                for (int nt = 0; nt < 4; nt++)
                    mma_f16(acc[mt][nt], afr[mt], &bfr[nt >> 1][(nt & 1) * 2]);
        }
    }

#pragma unroll
    for (int mt = 0; mt < 2; mt++) {
        const int d0 = dbase + wm * 32 + mt * 16 + g2;
#pragma unroll
        for (int nt = 0; nt < 4; nt++) {
            const int cl = wn * 32 + nt * 8 + t2 * 2;
            *reinterpret_cast<float2*>(&g_ysU[(size_t)d0 * NN + jbase + cl]) =
                make_float2(acc[mt][nt][0], acc[mt][nt][1]);
            *reinterpret_cast<float2*>(&g_ysU[(size_t)(d0 + 8) * NN + jbase + cl]) =
                make_float2(acc[mt][nt][2], acc[mt][nt][3]);
        }
    }
}

// ============================================================================
// Kernel B (secondary, PDL): inv_deg + fp16 A copy. Reads NOTHING xwU writes,
// so it runs concurrently with xwU (no cudaGridDependencySynchronize needed).
// ============================================================================
__global__ void __launch_bounds__(256) rowsum_kernel(const float* __restrict__ A) {
    int row = blockIdx.x;
    const float4* r4 = reinterpret_cast<const float4*>(A + (size_t)row * NN);
    __half* ah = g_Ah + (size_t)row * NN;
    float s = 0.f;
#pragma unroll
    for (int it = 0; it < (NN / 4) / 256; it++) {
        int idx = it * 256 + threadIdx.x;
        float4 v = r4[idx];
        s += (v.x + v.y) + (v.z + v.w);
        union { __half2 h[2]; uint2 u; } p;
        p.h[0] = __floats2half2_rn(v.x, v.y);
        p.h[1] = __floats2half2_rn(v.z, v.w);
        *reinterpret_cast<uint2*>(ah + (size_t)idx * 4) = p.u;
    }
    __shared__ float red[256];
    red[threadIdx.x] = s;
    __syncthreads();
#pragma unroll
    for (int o = 128; o > 0; o >>= 1) {
        if (threadIdx.x < o) red[threadIdx.x] += red[threadIdx.x + o];
        __syncthreads();
    }
    if (threadIdx.x == 0) g_inv_deg[row] = 1.0f / red[0];
}

// ============================================================================
// Kernel C: Y[d][j] = fp16( U[d][j] * inv_deg[j] * YSCALE )   (~20 MB, ~3us)
// ============================================================================
__global__ void __launch_bounds__(256) scaley_kernel() {
    const int d  = blockIdx.x >> 1;
    const int j0 = (blockIdx.x & 1) * 4096 + threadIdx.x * 16;
    const float* u = g_ysU + (size_t)d * NN + j0;
    __half* y = g_ysTh + (size_t)d * NN + j0;
#pragma unroll
    for (int v = 0; v < 4; v++) {
        float4 uu = *reinterpret_cast<const float4*>(u + v * 4);
        float4 iv = *reinterpret_cast<const float4*>(g_inv_deg + j0 + v * 4);
        union { __half2 h[2]; uint2 w; } p;
        p.h[0] = __floats2half2_rn(uu.x * iv.x * YSCALE, uu.y * iv.y * YSCALE);
        p.h[1] = __floats2half2_rn(uu.z * iv.z * YSCALE, uu.w * iv.w * YSCALE);
        *reinterpret_cast<uint2*>(y + v * 4) = p.w;
    }
}

// ============================================================================
// Kernel D: out = relu( (inv_deg_i/YSCALE) * (Ah @ Yh) + bias )
// fp16 mma.sync m16n8k16: BM=128, BN=128, BK=64, 3-stage cp.async, 512 thr.
// Warp grid 4x4, warp tile 32x32. Grid 64x2 = 128 CTAs (single wave). [R11]
// ============================================================================
constexpr int BM = 128, BN = 128, BK = 64;
constexpr int STAGES = 3;
constexpr int NK = NN / BK;                   // 128
constexpr int ROWH = (BK + 8) * 2;            // 144
constexpr int TILE_B = 128 * ROWH;            // 18432
constexpr int STAGE_B = 2 * TILE_B;           // 36864
constexpr int SMEM_GEMM = STAGES * STAGE_B + 2 * BM * 4;

__global__ void __launch_bounds__(512, 1) gcn_gemm_kernel(const float* __restrict__ bias,
                                                          float* __restrict__ out) {
    extern __shared__ char smem[];
    const uint32_t sbase = smem_u32(smem);
    float* invd_s = reinterpret_cast<float*>(smem + STAGES * STAGE_B);
    float* bias_s = invd_s + BM;

    const int tid  = threadIdx.x;
    const int wid  = tid >> 5;
    const int lane = tid & 31;
    const int wm   = wid >> 2;
    const int wn   = wid & 3;
    const int mbase = blockIdx.x * BM;
    const int nbase = blockIdx.y * BN;

    if (tid < BM) {
        invd_s[tid] = g_inv_deg[mbase + tid] * (1.0f / YSCALE);
        bias_s[tid] = bias[nbase + tid];
    }

    const int g2 = lane >> 2, t2 = lane & 3;
    const int q = lane >> 3, r = lane & 7;
    const uint32_t aoff = (uint32_t)((wm * 32 + (q & 1) * 8 + r) * ROWH + (q >> 1) * 16);
    const uint32_t boff = (uint32_t)((wn * 32 + (q >> 1) * 8 + r) * ROWH + (q & 1) * 16);

    auto load_stage = [&](int st, int kt) {
        const uint32_t sA = sbase + st * STAGE_B;
        const uint32_t sB = sA + TILE_B;
        const int k0 = kt * BK;
#pragma unroll
        for (int i = 0; i < 4; i++) {
            int c = i * 512 + tid;            // 0..2047
            if (c < 1024) {
                int row = c >> 3, cq = c & 7;
                cp16(sA + row * ROWH + cq * 16,
                     g_Ah + (size_t)(mbase + row) * NN + k0 + cq * 8);
            } else {
                int c2 = c - 1024;
                int row = c2 >> 3, cq = c2 & 7;
                cp16(sB + row * ROWH + cq * 16,
                     g_ysTh + (size_t)(nbase + row) * NN + k0 + cq * 8);
            }
        }
    };

    float acc[2][4][4];
#pragma unroll
    for (int mt = 0; mt < 2; mt++)
#pragma unroll
        for (int nt = 0; nt < 4; nt++)
#pragma unroll
            for (int i = 0; i < 4; i++) acc[mt][nt][i] = 0.f;

    load_stage(0, 0); cp_commit();
    load_stage(1, 1); cp_commit();

    int st = 0;
    for (int kt = 0; kt < NK; kt++) {
        cp_wait<1>();
        __syncthreads();

        int pst = st + 2 >= STAGES ? st + 2 - STAGES : st + 2;
        if (kt + 2 < NK) load_stage(pst, kt + 2);
        cp_commit();

        const uint32_t sA = sbase + st * STAGE_B;
        const uint32_t sB = sA + TILE_B;
#pragma unroll
        for (int ks = 0; ks < 4; ks++) {
            uint32_t afr[2][4];
#pragma unroll
            for (int mt = 0; mt < 2; mt++)
                ldsm4(afr[mt], sA + aoff + mt * (16 * ROWH) + ks * 32);
            uint32_t bfr[2][4];
#pragma unroll
            for (int np = 0; np < 2; np++)
                ldsm4(bfr[np], sB + boff + np * (16 * ROWH) + ks * 32);
#pragma unroll
            for (int mt = 0; mt < 2; mt++)
#pragma unroll
                for (int nt = 0; nt < 4; nt++)
                    mma_f16(acc[mt][nt], afr[mt], &bfr[nt >> 1][(nt & 1) * 2]);
        }
        st = st + 1 >= STAGES ? 0 : st + 1;
    }

#pragma unroll
    for (int mt = 0; mt < 2; mt++) {
        const int rl = wm * 32 + mt * 16 + g2;
        const float s0 = invd_s[rl], s1 = invd_s[rl + 8];
        float* o0 = out + (size_t)(mbase + rl) * DF + nbase + wn * 32;
        float* o1 = o0 + (size_t)8 * DF;
#pragma unroll
        for (int nt = 0; nt < 4; nt++) {
            const int c = nt * 8 + t2 * 2;
            const float b0 = bias_s[wn * 32 + c], b1 = bias_s[wn * 32 + c + 1];
            float2 v0, v1;
            v0.x = fmaxf(fmaf(acc[mt][nt][0], s0, b0), 0.f);
            v0.y = fmaxf(fmaf(acc[mt][nt][1], s0, b1), 0.f);
            v1.x = fmaxf(fmaf(acc[mt][nt][2], s1, b0), 0.f);
            v1.y = fmaxf(fmaf(acc[mt][nt][3], s1, b1), 0.f);
            *reinterpret_cast<float2*>(o0 + c) = v0;
            *reinterpret_cast<float2*>(o1 + c) = v1;
        }
    }
}

// ============================================================================
// Launch: xwU (PDL primary) -> rowsum (PDL secondary, overlaps) -> scaleY -> GEMM
// ============================================================================
extern "C" void kernel_launch(void* const* d_in, const int* in_sizes, int n_in,
                              void* d_out, int out_size) {
    const float* x    = (const float*)d_in[0];   // [8192,256]
    const float* adj  = (const float*)d_in[1];   // [8192,8192]
    const float* W    = (const float*)d_in[2];   // [256,256]
    const float* bias = (const float*)d_in[3];   // [256]
    float* out = (float*)d_out;                  // [8192,256]

    cudaFuncSetAttribute(gcn_gemm_kernel, cudaFuncAttributeMaxDynamicSharedMemorySize,
                         SMEM_GEMM);
    cudaFuncSetAttribute(xwU_kernel, cudaFuncAttributeMaxDynamicSharedMemorySize,
                         SMEM_XW);

    // primary: U matmul (independent of rowsum)
    xwU_kernel<<<128, 512, SMEM_XW>>>(x, W);

    // secondary: rowsum with programmatic stream serialization -> overlaps xwU
    {
        cudaLaunchConfig_t cfg = {};
        cfg.gridDim  = dim3(NN, 1, 1);
        cfg.blockDim = dim3(256, 1, 1);
        cfg.dynamicSmemBytes = 0;
        cfg.stream = 0;
        cudaLaunchAttribute attr[1];
        attr[0].id = cudaLaunchAttributeProgrammaticStreamSerialization;
        attr[0].val.programmaticStreamSerializationAllowed = 1;
        cfg.attrs = attr;
        cfg.numAttrs = 1;
        cudaLaunchKernelEx(&cfg, rowsum_kernel, adj);
    }

    scaley_kernel<<<512, 256>>>();
    dim3 grid(NN / BM, DF / BN);      // 64 x 2
    gcn_gemm_kernel<<<grid, 512, SMEM_GEMM>>>(bias, out);
}